// round 2
// baseline (speedup 1.0000x reference)
#include <cuda_runtime.h>

#define R_ 64
#define I_ 256
#define O_ 256
#define NB 8
#define TPB 256

// W_sum[r, o] = sum_i W[r, i, o]   (64 x 256 fp32 = 64 KB scratch)
__device__ float g_wsum[R_ * O_];

__global__ void wsum_kernel(const float* __restrict__ W) {
    int r = blockIdx.x;
    int o = threadIdx.x;
    const float* p = W + (size_t)r * I_ * O_ + o;
    float s = 0.f;
#pragma unroll 8
    for (int i = 0; i < I_; ++i) s += p[(size_t)i * O_];
    g_wsum[r * O_ + o] = s;
}

__device__ __forceinline__ unsigned long long dup2(float f) {
    unsigned long long d;
    asm("mov.b64 %0, {%1, %1};" : "=l"(d) : "f"(f));
    return d;
}
__device__ __forceinline__ void fma2(unsigned long long& d,
                                     unsigned long long a,
                                     unsigned long long b) {
    asm("fma.rn.f32x2 %0, %1, %2, %0;" : "+l"(d) : "l"(a), "l"(b));
}
__device__ __forceinline__ float2 unpk(unsigned long long v) {
    float lo, hi;
    asm("mov.b64 {%0, %1}, %2;" : "=f"(lo), "=f"(hi) : "l"(v));
    return make_float2(lo, hi);
}

__global__ __launch_bounds__(TPB, 1) void rgcn_kernel(
    const float* __restrict__ x, const float* __restrict__ cs,
    float* __restrict__ out, int E)
{
    // double-buffered per-chunk operands
    __shared__ float s_rcs[2][R_][NB];   // 1/cs, entity-contiguous per r
    __shared__ float s_xsum[2][NB];

    const int tid = threadIdx.x;
    const int wid = tid >> 5;
    const int lid = tid & 31;

    // Thread owns output column `tid`; W_sum column duplicated into f32x2 regs.
    unsigned long long wd[R_];
#pragma unroll
    for (int r = 0; r < R_; ++r) wd[r] = dup2(g_wsum[r * O_ + tid]);

    const int nchunks = (E + NB - 1) / NB;

    // register staging for the next chunk (prefetch hides DRAM latency)
    float4 xa, xb;
    float c0, c1;
    const int r0  = tid & 63;
    const int el0 = tid >> 6;      // entity-in-chunk for cs word 0
    const int el1 = el0 + 4;       // (tid+256): same r, entity + 4

    auto STAGE = [&](int chunk) {
        // x row for entity (chunk*NB + wid), one warp per entity
        long e = (long)chunk * NB + wid;
        if (e < E) {
            const float4* xp = reinterpret_cast<const float4*>(x + e * (long)I_);
            xa = xp[lid];
            xb = xp[lid + 32];
        } else {
            xa = make_float4(0.f, 0.f, 0.f, 0.f);
            xb = xa;
        }
        // cs: 512 contiguous floats for the chunk, 2 per thread, coalesced
        long eb = (long)chunk * NB;
        long ea = eb + el0, ec = eb + el1;
        c0 = (ea < E) ? cs[ea * (long)R_ + r0] : 1.f;
        c1 = (ec < E) ? cs[ec * (long)R_ + r0] : 1.f;
    };

    auto PROCESS = [&](int b) {
        s_rcs[b][r0][el0] = 1.0f / c0;
        s_rcs[b][r0][el1] = 1.0f / c1;
        float v = (xa.x + xa.y) + (xa.z + xa.w) +
                  (xb.x + xb.y) + (xb.z + xb.w);
#pragma unroll
        for (int off = 16; off; off >>= 1)
            v += __shfl_xor_sync(0xffffffffu, v, off);
        if (lid == 0) s_xsum[b][wid] = v;
    };

    int chunk = blockIdx.x;
    if (chunk >= nchunks) return;

    STAGE(chunk);
    PROCESS(0);
    __syncthreads();

    int buf = 0;
    for (; chunk < nchunks; chunk += gridDim.x) {
        int nxt = chunk + gridDim.x;
        bool have_next = (nxt < nchunks);
        if (have_next) STAGE(nxt);   // LDGs issued before the long GEMM phase

        // GEMM phase: 8 entities x 256 cols, entity-pairs packed in f32x2.
        // Per r: 2x LDS.128 (broadcast, 4 ready pairs) + 4x FFMA2.
        unsigned long long a0 = 0, a1 = 0, a2 = 0, a3 = 0;
#pragma unroll
        for (int r = 0; r < R_; ++r) {
            ulonglong2 p01 = *reinterpret_cast<const ulonglong2*>(&s_rcs[buf][r][0]);
            ulonglong2 p23 = *reinterpret_cast<const ulonglong2*>(&s_rcs[buf][r][4]);
            fma2(a0, p01.x, wd[r]);
            fma2(a1, p01.y, wd[r]);
            fma2(a2, p23.x, wd[r]);
            fma2(a3, p23.y, wd[r]);
        }

        // epilogue: scale by x_sum, store (coalesced 1 KB rows)
        long e0 = (long)chunk * NB;
        float2 f0 = unpk(a0), f1 = unpk(a1), f2 = unpk(a2), f3 = unpk(a3);
        float vals[NB] = {f0.x, f0.y, f1.x, f1.y, f2.x, f2.y, f3.x, f3.y};
#pragma unroll
        for (int k = 0; k < NB; ++k) {
            long e = e0 + k;
            if (e < E) out[e * (long)O_ + tid] = vals[k] * s_xsum[buf][k];
        }

        if (have_next) PROCESS(buf ^ 1);
        __syncthreads();
        buf ^= 1;
    }
}

extern "C" void kernel_launch(void* const* d_in, const int* in_sizes, int n_in,
                              void* d_out, int out_size) {
    const float* x  = (const float*)d_in[0];
    const float* cs = (const float*)d_in[1];
    const float* W  = (const float*)d_in[2];
    // d_in[3] = edge_index : dead in the reference computation, never read.
    float* out = (float*)d_out;

    int E = in_sizes[1] / R_;   // cs is (E, 64)

    wsum_kernel<<<R_, O_>>>(W);
    rgcn_kernel<<<152, TPB>>>(x, cs, out, E);
}

// round 4
// speedup vs baseline: 1.4710x; 1.4710x over previous
#include <cuda_runtime.h>

#define R_   64
#define I_   256
#define O_   256
#define MT   128          // entities per tile
#define TPB  256
#define GRID 152

// W_sum[r, o] = sum_i W[r, i, o]  (64 x 256 fp32, 16B-aligned for vector views)
__device__ __align__(16) float g_wsum[R_ * O_];

__global__ void wsum_kernel(const float* __restrict__ W) {
    int r = blockIdx.x;
    int o = threadIdx.x;
    const float* p = W + (size_t)r * I_ * O_ + o;
    float s = 0.f;
#pragma unroll 8
    for (int i = 0; i < I_; ++i) s += p[(size_t)i * O_];
    g_wsum[r * O_ + o] = s;
}

__device__ __forceinline__ unsigned long long dup2(float f) {
    unsigned long long d;
    asm("mov.b64 %0, {%1, %1};" : "=l"(d) : "f"(f));
    return d;
}
__device__ __forceinline__ void fma2(unsigned long long& d,
                                     unsigned long long a,
                                     unsigned long long b) {
    asm("fma.rn.f32x2 %0, %1, %2, %0;" : "+l"(d) : "l"(a), "l"(b));
}
__device__ __forceinline__ float2 unpk(unsigned long long v) {
    float lo, hi;
    asm("mov.b64 {%0, %1}, %2;" : "=f"(lo), "=f"(hi) : "l"(v));
    return make_float2(lo, hi);
}

// Dynamic shared layout:
//   [0,      65536)  : s_b  u64[64][128]    W_sum as column-pairs (chunk-invariant)
//   [65536, 131072)  : s_a  f32[2][64][128] rcs, k-major, double-buffered
//   [131072,133120)  : s_xp f32[2][256]     per-thread partial x row-sums
#define SMEM_BYTES 133120

__global__ __launch_bounds__(TPB, 1) void rgcn_kernel(
    const float* __restrict__ x, const float* __restrict__ cs,
    float* __restrict__ out, int E)
{
    extern __shared__ __align__(16) char smem[];
    unsigned long long* s_b  = (unsigned long long*)smem;
    float*              s_a  = (float*)(smem + 65536);
    float*              s_xp = (float*)(smem + 131072);

    const int tid = threadIdx.x;
    const int tx  = tid & 15;     // column group
    const int ty  = tid >> 4;     // entity group

    // ---- load W_sum into shared once (row-major f32 == u64 column-pairs) ----
    {
        const float4* src = (const float4*)g_wsum;   // 4096 x 16B
        float4*       dst = (float4*)s_b;
        for (int i = tid; i < 4096; i += TPB) dst[i] = src[i];
    }

    const int nch = (E + MT - 1) / MT;

    // ---- stage one chunk: rcs -> s_a[buf] (k-major), x half-row-sum -> s_xp ----
    auto stage = [&](int chunk, int buf) {
        long e    = (long)chunk * MT + (tid >> 1);
        int  half = tid & 1;                    // which 32-r / 128-col half
        int  el   = tid >> 1;                   // entity-in-tile
        float* sa = s_a + buf * 8192;
        float xsum = 0.f;
        if (e < E) {
            const float4* cp = (const float4*)(cs + e * (long)R_ + half * 32);
#pragma unroll
            for (int i = 0; i < 8; ++i) {
                float4 v = cp[i];
                int kb = half * 32 + 4 * i;
                sa[(kb + 0) * 128 + el] = 1.0f / v.x;
                sa[(kb + 1) * 128 + el] = 1.0f / v.y;
                sa[(kb + 2) * 128 + el] = 1.0f / v.z;
                sa[(kb + 3) * 128 + el] = 1.0f / v.w;
            }
            // half x row = 128 floats = 32 float4 (R3 bug: was 8)
            const float4* xp4 = (const float4*)(x + e * (long)I_ + half * 128);
#pragma unroll
            for (int i = 0; i < 32; ++i) {
                float4 v = xp4[i];
                xsum += (v.x + v.y) + (v.z + v.w);
            }
        } else {
#pragma unroll
            for (int k = 0; k < 32; ++k) sa[(half * 32 + k) * 128 + el] = 0.f;
        }
        s_xp[buf * 256 + tid] = xsum;
    };

    int c0 = blockIdx.x;
    if (c0 < nch) stage(c0, 0);
    __syncthreads();

    int buf = 0;
    for (int chunk = c0; chunk < nch; chunk += GRID) {
        int nxt = chunk + GRID;
        if (nxt < nch) stage(nxt, buf ^ 1);   // overlap next-chunk LDG with GEMM

        // ---- GEMM: acc[i][j] = sum_k rcs[e_i,k] * wsum[k, colpair_j] ----
        unsigned long long acc[8][8];
#pragma unroll
        for (int i = 0; i < 8; ++i)
#pragma unroll
            for (int j = 0; j < 8; ++j) acc[i][j] = 0ull;

        const float* sa = s_a + buf * 8192;
#pragma unroll 16
        for (int k = 0; k < 64; ++k) {
            // A-frag: 8 entities (2x LDS.128, 2-addr broadcast per warp)
            float4 a0 = *(const float4*)(sa + k * 128 + ty * 8);
            float4 a1 = *(const float4*)(sa + k * 128 + ty * 8 + 4);
            unsigned long long ad[8];
            ad[0] = dup2(a0.x); ad[1] = dup2(a0.y);
            ad[2] = dup2(a0.z); ad[3] = dup2(a0.w);
            ad[4] = dup2(a1.x); ad[5] = dup2(a1.y);
            ad[6] = dup2(a1.z); ad[7] = dup2(a1.w);
            // B-frag: 8 column-pairs at stride 16 (conflict-free LDS.64)
            const unsigned long long* sb = s_b + k * 128 + tx;
#pragma unroll
            for (int j = 0; j < 8; ++j) {
                unsigned long long bv = sb[16 * j];
#pragma unroll
                for (int i = 0; i < 8; ++i) fma2(acc[i][j], ad[i], bv);
            }
        }

        // ---- epilogue: scale by x_sum, coalesced STG.64 ----
        long eb = (long)chunk * MT;
#pragma unroll
        for (int i = 0; i < 8; ++i) {
            long e = eb + ty * 8 + i;
            if (e < E) {
                int  es = (ty * 8 + i) * 2;
                float xs = s_xp[buf * 256 + es] + s_xp[buf * 256 + es + 1];
                float2* op = (float2*)(out + e * (long)O_);
#pragma unroll
                for (int j = 0; j < 8; ++j) {
                    float2 f = unpk(acc[i][j]);
                    f.x *= xs; f.y *= xs;
                    op[tx + 16 * j] = f;
                }
            }
        }

        __syncthreads();
        buf ^= 1;
    }
}

extern "C" void kernel_launch(void* const* d_in, const int* in_sizes, int n_in,
                              void* d_out, int out_size) {
    const float* x  = (const float*)d_in[0];
    const float* cs = (const float*)d_in[1];
    const float* W  = (const float*)d_in[2];
    // d_in[3] = edge_index : dead in the reference computation, never read.
    float* out = (float*)d_out;

    int E = in_sizes[1] / R_;   // cs is (E, 64)

    cudaFuncSetAttribute(rgcn_kernel,
                         cudaFuncAttributeMaxDynamicSharedMemorySize, SMEM_BYTES);

    wsum_kernel<<<R_, O_>>>(W);
    rgcn_kernel<<<GRID, TPB, SMEM_BYTES>>>(x, cs, out, E);
}